// round 5
// baseline (speedup 1.0000x reference)
#include <cuda_runtime.h>
#include <math.h>

#define W 64
#define ROWS_PER_CTA 8
#define THREADS_PER_ROW 16            // 16 threads x 4 cols (float4) = 64 cols
#define CTA_THREADS (ROWS_PER_CTA * THREADS_PER_ROW)

// Grid: B/ROWS_PER_CTA CTAs of 128 threads.
// Thread layout: r = tid>>4 (batch row within CTA), t = tid&15, columns 4t..4t+3.
// dep[b,i, 4t..4t+3] stored as one float4 -> 16 threads x 16B = 256B coalesced per (row,i).
// dep_matrix is write-once and larger than L2 -> streaming (.cs) stores.
__global__ void __launch_bounds__(CTA_THREADS) neural_ooo_kernel(
    const int* __restrict__ instructions,      // [B, W]
    const float* __restrict__ hazard_weights,  // [5]
    float* __restrict__ dep_out,               // [B, W, W]
    float* __restrict__ readiness_out)         // [B, W]
{
    __shared__ int s_key[ROWS_PER_CTA][W + 1];  // +1 pad: rows in different banks

    const int tid = threadIdx.x;
    const int r   = tid >> 4;          // batch row within CTA
    const int t   = tid & 15;          // column group
    const int j0  = t * 4;             // first of this thread's 4 columns
    const int b   = blockIdx.x * ROWS_PER_CTA + r;

    // int4 load lands exactly on this thread's own (row, 4 columns).
    const int4 iv = ((const int4*)instructions)[(size_t)blockIdx.x * (ROWS_PER_CTA * W / 4) + tid];
    const int inst[4] = {iv.x, iv.y, iv.z, iv.w};

    int rn[4], rm[4], rdj[4];
#pragma unroll
    for (int q = 0; q < 4; ++q) {
        const int rd = inst[q] & 31;
        rn[q]  = (inst[q] >> 5) & 31;
        rm[q]  = (inst[q] >> 16) & 31;
        // Different sentinels row-side vs col-side: rd==31 never matches anything.
        s_key[r][j0 + q] = (rd < 31) ? rd : 0x40;
        rdj[q]           = (rd < 31) ? rd : 0x80;
    }

    // 4-entry sigmoid LUT (score takes only 4 distinct values).
    const float w0 = hazard_weights[0];
    const float w2 = hazard_weights[2];
    const float w4 = hazard_weights[4];
    const float s00 = 1.0f / (1.0f + expf(-(w4)));
    const float s10 = 1.0f / (1.0f + expf(-(w0 + w4)));
    const float s01 = 1.0f / (1.0f + expf(-(w2 + w4)));
    const float s11 = 1.0f / (1.0f + expf(-(w0 + w2 + w4)));

    __syncthreads();

    float prod[4] = {1.0f, 1.0f, 1.0f, 1.0f};
    float4* __restrict__ row_out =
        (float4*)(dep_out + (size_t)b * (W * W)) + t;   // advance by W/4 per i

#pragma unroll
    for (int i = 0; i < W; ++i) {
        const int k = s_key[r][i];       // broadcast within each 16-thread group
        float4 d;
        float* dv = &d.x;
#pragma unroll
        for (int q = 0; q < 4; ++q) {
            const bool raw = (k == rn[q]) || (k == rm[q]);
            const bool waw = (k == rdj[q]);
            const float a   = raw ? s10 : s00;
            const float c   = raw ? s11 : s01;
            float dep = waw ? c : a;
            dep = (i < j0 + q) ? dep : 0.0f;           // strict upper triangle
            dv[q] = dep;
            prod[q] = fmaf(-dep, prod[q], prod[q]);    // prod *= (1 - dep)
        }
        __stcs(row_out + i * (W / 4), d);              // streaming store
    }

    const float4 rr = make_float4(prod[0], prod[1], prod[2], prod[3]);
    __stcs((float4*)(readiness_out + (size_t)b * W) + t, rr);
}

extern "C" void kernel_launch(void* const* d_in, const int* in_sizes, int n_in,
                              void* d_out, int out_size)
{
    // Expected metadata order: instructions[B*W], pc[B], opcode_table[256*32],
    // feat_W[12*32], feat_b[32], hazard_weights[5]. The embedding path is dead
    // code in the reference (del emb), so only instructions + hazard_weights
    // are live. Identify them by their UNIQUE sizes to be robust against any
    // input-ordering surprise: instructions is the largest input (B*W),
    // hazard_weights is the only 5-element input.
    int idx_inst = 0, idx_hw = -1, max_sz = -1;
    for (int i = 0; i < n_in; ++i) {
        if (in_sizes[i] > max_sz) { max_sz = in_sizes[i]; idx_inst = i; }
        if (in_sizes[i] == 5) idx_hw = i;
    }
    if (idx_hw < 0) idx_hw = n_in - 1;   // fallback: last input

    const int*   instructions   = (const int*)d_in[idx_inst];
    const float* hazard_weights = (const float*)d_in[idx_hw];

    const int B = in_sizes[idx_inst] / W;   // 8192

    float* dep_out       = (float*)d_out;                       // [B, W, W]
    float* readiness_out = (float*)d_out + (size_t)B * W * W;   // [B, W]

    neural_ooo_kernel<<<B / ROWS_PER_CTA, CTA_THREADS>>>(
        instructions, hazard_weights, dep_out, readiness_out);
}

// round 12
// speedup vs baseline: 1.0680x; 1.0680x over previous
#include <cuda_runtime.h>
#include <math.h>

#define W 64
#define ROWS_PER_CTA 8
#define THREADS_PER_ROW 32            // 16 col-groups (float4) x 2 i-halves
#define CTA_THREADS (ROWS_PER_CTA * THREADS_PER_ROW)   // 256

// Grid: B/8 = 1024 CTAs x 256 threads = 262K threads -> ~48-55 warps/SM.
// Warp == one batch row. lane = t + 16*h: t owns columns 4t..4t+3 (one float4
// store per i), h owns i in [32h, 32h+32). Readiness partials combine via
// shfl_xor(16). dep_matrix is write-once and bigger than L2 -> .cs stores.
__global__ void __launch_bounds__(CTA_THREADS) neural_ooo_kernel(
    const int* __restrict__ instructions,      // [B, W]
    const float* __restrict__ hazard_weights,  // [5]
    float* __restrict__ dep_out,               // [B, W, W]
    float* __restrict__ readiness_out)         // [B, W]
{
    __shared__ int s_key[ROWS_PER_CTA][W + 1];  // +1 pad

    const int tid  = threadIdx.x;
    const int r    = tid >> 5;         // batch row within CTA (warp id)
    const int lane = tid & 31;
    const int t    = lane & 15;        // column group
    const int h    = lane >> 4;        // i-half
    const int j0   = t * 4;
    const int b    = blockIdx.x * ROWS_PER_CTA + r;

    // Both halves load the same int4 (L1 broadcast) -> regs for 4 columns.
    const int4 iv = ((const int4*)(instructions + (size_t)b * W))[t];
    const int inst[4] = {iv.x, iv.y, iv.z, iv.w};

    int rn[4], rm[4], rdj[4];
#pragma unroll
    for (int q = 0; q < 4; ++q) {
        const int rd = inst[q] & 31;
        rn[q]  = (inst[q] >> 5) & 31;
        rm[q]  = (inst[q] >> 16) & 31;
        const int key = (rd < 31) ? rd : 0x40;   // row-side sentinel
        rdj[q]        = (rd < 31) ? rd : 0x80;   // col-side sentinel (never matches)
        if (h == 0) s_key[r][j0 + q] = key;
    }

    // 4-entry sigmoid LUT (score takes only 4 distinct values).
    const float w0 = hazard_weights[0];
    const float w2 = hazard_weights[2];
    const float w4 = hazard_weights[4];
    const float s00 = 1.0f / (1.0f + expf(-(w4)));
    const float s10 = 1.0f / (1.0f + expf(-(w0 + w4)));
    const float s01 = 1.0f / (1.0f + expf(-(w2 + w4)));
    const float s11 = 1.0f / (1.0f + expf(-(w0 + w2 + w4)));

    __syncthreads();

    const int ibase = h * 32;
    float prod[4] = {1.0f, 1.0f, 1.0f, 1.0f};
    float4* __restrict__ row_out =
        (float4*)(dep_out + (size_t)b * (W * W) + (size_t)ibase * W) + t;

#pragma unroll
    for (int ii = 0; ii < 32; ++ii) {
        const int i = ibase + ii;
        const int k = s_key[r][i];       // broadcast LDS
        float4 d;
        float* dv = &d.x;
#pragma unroll
        for (int q = 0; q < 4; ++q) {
            const bool raw = (k == rn[q]) || (k == rm[q]);
            const bool waw = (k == rdj[q]);
            const float a   = raw ? s10 : s00;
            const float c   = raw ? s11 : s01;
            float dep = waw ? c : a;
            dep = (i < j0 + q) ? dep : 0.0f;           // strict upper triangle
            dv[q] = dep;
            prod[q] = fmaf(-dep, prod[q], prod[q]);    // prod *= (1 - dep)
        }
        __stcs(row_out + ii * (W / 4), d);             // streaming STG.128
    }

    // Combine the two i-halves' partial products.
#pragma unroll
    for (int q = 0; q < 4; ++q)
        prod[q] *= __shfl_xor_sync(0xffffffffu, prod[q], 16);

    if (h == 0) {
        const float4 rr = make_float4(prod[0], prod[1], prod[2], prod[3]);
        __stcs((float4*)(readiness_out + (size_t)b * W) + t, rr);
    }
}

extern "C" void kernel_launch(void* const* d_in, const int* in_sizes, int n_in,
                              void* d_out, int out_size)
{
    // Live inputs only (embedding path is dead code: `del emb`). Identify by
    // unique sizes to be robust to ordering: instructions = largest input,
    // hazard_weights = the only 5-element input.
    int idx_inst = 0, idx_hw = -1, max_sz = -1;
    for (int i = 0; i < n_in; ++i) {
        if (in_sizes[i] > max_sz) { max_sz = in_sizes[i]; idx_inst = i; }
        if (in_sizes[i] == 5) idx_hw = i;
    }
    if (idx_hw < 0) idx_hw = n_in - 1;

    const int*   instructions   = (const int*)d_in[idx_inst];
    const float* hazard_weights = (const float*)d_in[idx_hw];

    const int B = in_sizes[idx_inst] / W;   // 8192

    float* dep_out       = (float*)d_out;                       // [B, W, W]
    float* readiness_out = (float*)d_out + (size_t)B * W * W;   // [B, W]

    neural_ooo_kernel<<<B / ROWS_PER_CTA, CTA_THREADS>>>(
        instructions, hazard_weights, dep_out, readiness_out);
}

// round 15
// speedup vs baseline: 1.1679x; 1.0935x over previous
#include <cuda_runtime.h>
#include <math.h>

#define W 64
#define ROWS_PER_CTA 8
#define CTA_THREADS (ROWS_PER_CTA * 32)   // 256

// Grid: B/8 = 1024 CTAs x 256 threads. Warp == one batch row.
// lane = t + 16*h: t owns columns 4t..4t+3 (one float4 store per i),
// h owns i in [32h, 32h+32). Readiness partials merge via shfl_xor(16).
// dep_matrix is write-once and bigger than L2 -> .cs streaming stores.
// __launch_bounds__(...,6): force regs <= ~42 so 6 CTAs/SM (48 warps) fit.
__global__ void __launch_bounds__(CTA_THREADS, 6) neural_ooo_kernel(
    const int* __restrict__ instructions,      // [B, W]
    const float* __restrict__ hazard_weights,  // [5]
    float* __restrict__ dep_out,               // [B, W, W]
    float* __restrict__ readiness_out)         // [B, W]
{
    __shared__ int s_key[ROWS_PER_CTA][W + 1];  // +1 pad

    const int tid  = threadIdx.x;
    const int r    = tid >> 5;         // batch row within CTA (warp id)
    const int lane = tid & 31;
    const int t    = lane & 15;        // column group
    const int h    = lane >> 4;        // i-half
    const int j0   = t * 4;
    const int b    = blockIdx.x * ROWS_PER_CTA + r;

    // Both halves load the same int4 (L1 broadcast) -> 4 columns in regs.
    const int4 iv = ((const int4*)(instructions + (size_t)b * W))[t];

    // Scalarized per-column fields (no arrays -> clean register promotion).
    const int rd0 = iv.x & 31, rd1 = iv.y & 31, rd2 = iv.z & 31, rd3 = iv.w & 31;
    const int rn0 = (iv.x >> 5) & 31, rn1 = (iv.y >> 5) & 31;
    const int rn2 = (iv.z >> 5) & 31, rn3 = (iv.w >> 5) & 31;
    const int rm0 = (iv.x >> 16) & 31, rm1 = (iv.y >> 16) & 31;
    const int rm2 = (iv.z >> 16) & 31, rm3 = (iv.w >> 16) & 31;
    // Sentinels: row-side key uses 0x40, col-side rdj uses 0x80 -> rd==31
    // can never match anything on either side.
    const int rdj0 = (rd0 < 31) ? rd0 : 0x80;
    const int rdj1 = (rd1 < 31) ? rd1 : 0x80;
    const int rdj2 = (rd2 < 31) ? rd2 : 0x80;
    const int rdj3 = (rd3 < 31) ? rd3 : 0x80;

    if (h == 0) {
        s_key[r][j0 + 0] = (rd0 < 31) ? rd0 : 0x40;
        s_key[r][j0 + 1] = (rd1 < 31) ? rd1 : 0x40;
        s_key[r][j0 + 2] = (rd2 < 31) ? rd2 : 0x40;
        s_key[r][j0 + 3] = (rd3 < 31) ? rd3 : 0x40;
    }

    // 4-entry sigmoid LUT (score takes only 4 distinct values).
    const float w0 = hazard_weights[0];
    const float w2 = hazard_weights[2];
    const float w4 = hazard_weights[4];
    const float s00 = 1.0f / (1.0f + expf(-(w4)));
    const float s10 = 1.0f / (1.0f + expf(-(w0 + w4)));
    const float s01 = 1.0f / (1.0f + expf(-(w2 + w4)));
    const float s11 = 1.0f / (1.0f + expf(-(w0 + w2 + w4)));

    __syncthreads();

    const int ibase = h * 32;
    float prod0 = 1.0f, prod1 = 1.0f, prod2 = 1.0f, prod3 = 1.0f;
    const int* __restrict__ krow = s_key[r];
    float4* __restrict__ row_out =
        (float4*)(dep_out + (size_t)b * (W * W) + (size_t)ibase * W) + t;

#pragma unroll
    for (int ii = 0; ii < 32; ++ii) {
        const int i = ibase + ii;
        const int k = krow[i];           // broadcast LDS

        bool raw, waw;
        float dep0, dep1, dep2, dep3;

        raw = (k == rn0) || (k == rm0);
        waw = (k == rdj0);
        dep0 = waw ? (raw ? s11 : s01) : (raw ? s10 : s00);
        dep0 = (i < j0 + 0) ? dep0 : 0.0f;

        raw = (k == rn1) || (k == rm1);
        waw = (k == rdj1);
        dep1 = waw ? (raw ? s11 : s01) : (raw ? s10 : s00);
        dep1 = (i < j0 + 1) ? dep1 : 0.0f;

        raw = (k == rn2) || (k == rm2);
        waw = (k == rdj2);
        dep2 = waw ? (raw ? s11 : s01) : (raw ? s10 : s00);
        dep2 = (i < j0 + 2) ? dep2 : 0.0f;

        raw = (k == rn3) || (k == rm3);
        waw = (k == rdj3);
        dep3 = waw ? (raw ? s11 : s01) : (raw ? s10 : s00);
        dep3 = (i < j0 + 3) ? dep3 : 0.0f;

        prod0 = fmaf(-dep0, prod0, prod0);
        prod1 = fmaf(-dep1, prod1, prod1);
        prod2 = fmaf(-dep2, prod2, prod2);
        prod3 = fmaf(-dep3, prod3, prod3);

        __stcs(row_out + ii * (W / 4), make_float4(dep0, dep1, dep2, dep3));
    }

    // Combine the two i-halves' partial products.
    prod0 *= __shfl_xor_sync(0xffffffffu, prod0, 16);
    prod1 *= __shfl_xor_sync(0xffffffffu, prod1, 16);
    prod2 *= __shfl_xor_sync(0xffffffffu, prod2, 16);
    prod3 *= __shfl_xor_sync(0xffffffffu, prod3, 16);

    if (h == 0) {
        __stcs((float4*)(readiness_out + (size_t)b * W) + t,
               make_float4(prod0, prod1, prod2, prod3));
    }
}

extern "C" void kernel_launch(void* const* d_in, const int* in_sizes, int n_in,
                              void* d_out, int out_size)
{
    // Live inputs only (embedding path is dead code: `del emb`). Identify by
    // unique sizes: instructions = largest input, hazard_weights = the only
    // 5-element input.
    int idx_inst = 0, idx_hw = -1, max_sz = -1;
    for (int i = 0; i < n_in; ++i) {
        if (in_sizes[i] > max_sz) { max_sz = in_sizes[i]; idx_inst = i; }
        if (in_sizes[i] == 5) idx_hw = i;
    }
    if (idx_hw < 0) idx_hw = n_in - 1;

    const int*   instructions   = (const int*)d_in[idx_inst];
    const float* hazard_weights = (const float*)d_in[idx_hw];

    const int B = in_sizes[idx_inst] / W;   // 8192

    float* dep_out       = (float*)d_out;                       // [B, W, W]
    float* readiness_out = (float*)d_out + (size_t)B * W * W;   // [B, W]

    neural_ooo_kernel<<<B / ROWS_PER_CTA, CTA_THREADS>>>(
        instructions, hazard_weights, dep_out, readiness_out);
}

// round 16
// speedup vs baseline: 1.2298x; 1.0530x over previous
#include <cuda_runtime.h>
#include <math.h>

#define W 64
#define ROWS_PER_CTA 2
#define CTA_THREADS (ROWS_PER_CTA * 32)   // 64

// Grid: B/2 = 4096 small CTAs -> fine-grained wave packing (R15 showed a 2x
// wave-quantization tail with 1024 large CTAs: 888 resident slots, 136 ran a
// second full CTA). 64-thread CTAs: ~25 resident/SM (40 regs) -> ~3700 slots,
// tail is one 4x-shorter CTA. Warp == one batch row. lane = t + 16*h: t owns
// columns 4t..4t+3 (one float4 store per i), h owns i in [32h, 32h+32).
// Readiness partials merge via shfl_xor(16). dep_matrix is write-once and
// bigger than L2 -> .cs streaming stores.
__global__ void __launch_bounds__(CTA_THREADS) neural_ooo_kernel(
    const int* __restrict__ instructions,      // [B, W]
    const float* __restrict__ hazard_weights,  // [5]
    float* __restrict__ dep_out,               // [B, W, W]
    float* __restrict__ readiness_out)         // [B, W]
{
    __shared__ int s_key[ROWS_PER_CTA][W + 1];  // +1 pad

    const int tid  = threadIdx.x;
    const int r    = tid >> 5;         // batch row within CTA (warp id)
    const int lane = tid & 31;
    const int t    = lane & 15;        // column group
    const int h    = lane >> 4;        // i-half
    const int j0   = t * 4;
    const int b    = blockIdx.x * ROWS_PER_CTA + r;

    // Both halves load the same int4 (L1 broadcast) -> 4 columns in regs.
    const int4 iv = ((const int4*)(instructions + (size_t)b * W))[t];

    // Scalarized per-column fields (clean register promotion).
    const int rd0 = iv.x & 31, rd1 = iv.y & 31, rd2 = iv.z & 31, rd3 = iv.w & 31;
    const int rn0 = (iv.x >> 5) & 31, rn1 = (iv.y >> 5) & 31;
    const int rn2 = (iv.z >> 5) & 31, rn3 = (iv.w >> 5) & 31;
    const int rm0 = (iv.x >> 16) & 31, rm1 = (iv.y >> 16) & 31;
    const int rm2 = (iv.z >> 16) & 31, rm3 = (iv.w >> 16) & 31;
    // Sentinels: row-side key uses 0x40, col-side rdj uses 0x80 -> rd==31
    // can never match anything on either side.
    const int rdj0 = (rd0 < 31) ? rd0 : 0x80;
    const int rdj1 = (rd1 < 31) ? rd1 : 0x80;
    const int rdj2 = (rd2 < 31) ? rd2 : 0x80;
    const int rdj3 = (rd3 < 31) ? rd3 : 0x80;

    if (h == 0) {
        s_key[r][j0 + 0] = (rd0 < 31) ? rd0 : 0x40;
        s_key[r][j0 + 1] = (rd1 < 31) ? rd1 : 0x40;
        s_key[r][j0 + 2] = (rd2 < 31) ? rd2 : 0x40;
        s_key[r][j0 + 3] = (rd3 < 31) ? rd3 : 0x40;
    }

    // 4-entry sigmoid LUT (score takes only 4 distinct values).
    const float w0 = hazard_weights[0];
    const float w2 = hazard_weights[2];
    const float w4 = hazard_weights[4];
    const float s00 = 1.0f / (1.0f + expf(-(w4)));
    const float s10 = 1.0f / (1.0f + expf(-(w0 + w4)));
    const float s01 = 1.0f / (1.0f + expf(-(w2 + w4)));
    const float s11 = 1.0f / (1.0f + expf(-(w0 + w2 + w4)));

    __syncthreads();

    const int ibase = h * 32;
    float prod0 = 1.0f, prod1 = 1.0f, prod2 = 1.0f, prod3 = 1.0f;
    const int* __restrict__ krow = s_key[r];
    float4* __restrict__ row_out =
        (float4*)(dep_out + (size_t)b * (W * W) + (size_t)ibase * W) + t;

#pragma unroll
    for (int ii = 0; ii < 32; ++ii) {
        const int i = ibase + ii;
        const int k = krow[i];           // broadcast LDS

        bool raw, waw;
        float dep0, dep1, dep2, dep3;

        raw = (k == rn0) || (k == rm0);
        waw = (k == rdj0);
        dep0 = waw ? (raw ? s11 : s01) : (raw ? s10 : s00);
        dep0 = (i < j0 + 0) ? dep0 : 0.0f;

        raw = (k == rn1) || (k == rm1);
        waw = (k == rdj1);
        dep1 = waw ? (raw ? s11 : s01) : (raw ? s10 : s00);
        dep1 = (i < j0 + 1) ? dep1 : 0.0f;

        raw = (k == rn2) || (k == rm2);
        waw = (k == rdj2);
        dep2 = waw ? (raw ? s11 : s01) : (raw ? s10 : s00);
        dep2 = (i < j0 + 2) ? dep2 : 0.0f;

        raw = (k == rn3) || (k == rm3);
        waw = (k == rdj3);
        dep3 = waw ? (raw ? s11 : s01) : (raw ? s10 : s00);
        dep3 = (i < j0 + 3) ? dep3 : 0.0f;

        prod0 = fmaf(-dep0, prod0, prod0);
        prod1 = fmaf(-dep1, prod1, prod1);
        prod2 = fmaf(-dep2, prod2, prod2);
        prod3 = fmaf(-dep3, prod3, prod3);

        __stcs(row_out + ii * (W / 4), make_float4(dep0, dep1, dep2, dep3));
    }

    // Combine the two i-halves' partial products.
    prod0 *= __shfl_xor_sync(0xffffffffu, prod0, 16);
    prod1 *= __shfl_xor_sync(0xffffffffu, prod1, 16);
    prod2 *= __shfl_xor_sync(0xffffffffu, prod2, 16);
    prod3 *= __shfl_xor_sync(0xffffffffu, prod3, 16);

    if (h == 0) {
        __stcs((float4*)(readiness_out + (size_t)b * W) + t,
               make_float4(prod0, prod1, prod2, prod3));
    }
}

extern "C" void kernel_launch(void* const* d_in, const int* in_sizes, int n_in,
                              void* d_out, int out_size)
{
    // Live inputs only (embedding path is dead code: `del emb`). Identify by
    // unique sizes: instructions = largest input, hazard_weights = the only
    // 5-element input.
    int idx_inst = 0, idx_hw = -1, max_sz = -1;
    for (int i = 0; i < n_in; ++i) {
        if (in_sizes[i] > max_sz) { max_sz = in_sizes[i]; idx_inst = i; }
        if (in_sizes[i] == 5) idx_hw = i;
    }
    if (idx_hw < 0) idx_hw = n_in - 1;

    const int*   instructions   = (const int*)d_in[idx_inst];
    const float* hazard_weights = (const float*)d_in[idx_hw];

    const int B = in_sizes[idx_inst] / W;   // 8192

    float* dep_out       = (float*)d_out;                       // [B, W, W]
    float* readiness_out = (float*)d_out + (size_t)B * W * W;   // [B, W]

    neural_ooo_kernel<<<B / ROWS_PER_CTA, CTA_THREADS>>>(
        instructions, hazard_weights, dep_out, readiness_out);
}